// round 3
// baseline (speedup 1.0000x reference)
#include <cuda_runtime.h>
#include <stdint.h>
#include <math.h>

#define Bz 128
#define Sz 400
#define Ez 512
#define Hz 512
#define H3 1536
#define Vz 50000
#define C2H 1024

#define OUT_HID  ((size_t)Bz*Vz)
#define OUT_ATTN (OUT_HID + (size_t)Bz*Hz)
#define OUT_PPTR (OUT_ATTN + (size_t)Bz*Sz)

__device__ float g_gi[Bz*H3];
__device__ float g_gh[Bz*H3];
__device__ float g_hnew[Bz*Hz];
__device__ float g_v[Bz*Hz];
__device__ float g_comb[Bz*C2H];
__device__ float g_attn[Sz*Bz];
__device__ float g_logits[(size_t)Bz*Vz];
__device__ float g_pptr[Bz];
__device__ float g_mx[Bz];
__device__ float g_inv[Bz];

__device__ __forceinline__ float sigf(float x) { return 1.f / (1.f + expf(-x)); }

// ---------------------------------------------------------------------------
// K1: gi = emb @ W_ih^T + b_ih (blockIdx.y=0) ; gh = h @ W_hh^T + b_hh (y=1)
// ---------------------------------------------------------------------------
__global__ void __launch_bounds__(128) gemm_gru(
    const float* __restrict__ emb, const float* __restrict__ Wih,
    const float* __restrict__ bih, const float* __restrict__ hid,
    const float* __restrict__ Whh, const float* __restrict__ bhh)
{
    const float* A    = blockIdx.y ? hid  : emb;
    const float* Bm   = blockIdx.y ? Whh  : Wih;
    const float* bias = blockIdx.y ? bhh  : bih;
    float* C          = blockIdx.y ? g_gh : g_gi;

    __shared__ float As[32][132];
    __shared__ float Bs[32][16];
    int tid = threadIdx.x;
    int nb = blockIdx.x * 16;
    int m0 = (tid >> 3) * 8;
    int n0 = (tid & 7) * 2;
    float acc[8][2] = {};
    for (int k0 = 0; k0 < 512; k0 += 32) {
        __syncthreads();
#pragma unroll
        for (int i = 0; i < 8; i++) {
            int lin = tid + i * 128;
            int m = lin >> 3, k4 = lin & 7;
            float4 a = *(const float4*)(A + (size_t)m * 512 + k0 + k4 * 4);
            As[k4*4+0][m]=a.x; As[k4*4+1][m]=a.y; As[k4*4+2][m]=a.z; As[k4*4+3][m]=a.w;
        }
        {
            int n = tid >> 3, k4 = tid & 7;
            float4 b = *(const float4*)(Bm + (size_t)(nb+n) * 512 + k0 + k4 * 4);
            Bs[k4*4+0][n]=b.x; Bs[k4*4+1][n]=b.y; Bs[k4*4+2][n]=b.z; Bs[k4*4+3][n]=b.w;
        }
        __syncthreads();
#pragma unroll
        for (int k = 0; k < 32; k++) {
            float4 a0 = *(const float4*)&As[k][m0];
            float4 a1 = *(const float4*)&As[k][m0+4];
            float2 bb = *(const float2*)&Bs[k][n0];
            float a[8] = {a0.x,a0.y,a0.z,a0.w,a1.x,a1.y,a1.z,a1.w};
#pragma unroll
            for (int i = 0; i < 8; i++) { acc[i][0] += a[i]*bb.x; acc[i][1] += a[i]*bb.y; }
        }
    }
    float b0v = bias[nb+n0], b1v = bias[nb+n0+1];
#pragma unroll
    for (int i = 0; i < 8; i++) {
        C[(size_t)(m0+i)*H3 + nb+n0]   = acc[i][0] + b0v;
        C[(size_t)(m0+i)*H3 + nb+n0+1] = acc[i][1] + b1v;
    }
}

// ---------------------------------------------------------------------------
// K2: GRU gates -> h_new; writes g_hnew, g_comb[:, :H], out hidden region
// ---------------------------------------------------------------------------
__global__ void gru_gates(const float* __restrict__ hidden, float* __restrict__ out)
{
    int b = blockIdx.x, h = threadIdx.x;
    size_t r3 = (size_t)b * H3;
    float ir = g_gi[r3 + h],        hr = g_gh[r3 + h];
    float iz = g_gi[r3 + Hz + h],   hz = g_gh[r3 + Hz + h];
    float in_= g_gi[r3 + 2*Hz + h], hn = g_gh[r3 + 2*Hz + h];
    float r = sigf(ir + hr);
    float z = sigf(iz + hz);
    float n = tanhf(in_ + r * hn);
    float hp = hidden[(size_t)b * Hz + h];
    float hx = (1.f - z) * n + z * hp;
    g_hnew[(size_t)b * Hz + h] = hx;
    g_comb[(size_t)b * C2H + h] = hx;
    out[OUT_HID + (size_t)b * Hz + h] = hx;
}

// ---------------------------------------------------------------------------
// K3: v = h_new @ W_bil[0]   (v[b][n] = sum_k h[b][k]*W[k][n])
// ---------------------------------------------------------------------------
__global__ void __launch_bounds__(128) gemm_v(const float* __restrict__ Wbil)
{
    __shared__ float As[32][132];
    __shared__ float Bs[32][16];
    int tid = threadIdx.x;
    int nb = blockIdx.x * 16;
    int m0 = (tid >> 3) * 8;
    int n0 = (tid & 7) * 2;
    float acc[8][2] = {};
    for (int k0 = 0; k0 < 512; k0 += 32) {
        __syncthreads();
#pragma unroll
        for (int i = 0; i < 8; i++) {
            int lin = tid + i * 128;
            int m = lin >> 3, k4 = lin & 7;
            float4 a = *(const float4*)(g_hnew + (size_t)m * 512 + k0 + k4 * 4);
            As[k4*4+0][m]=a.x; As[k4*4+1][m]=a.y; As[k4*4+2][m]=a.z; As[k4*4+3][m]=a.w;
        }
        {
            int n4 = tid & 3, k = tid >> 2;
            float4 b = *(const float4*)(Wbil + (size_t)(k0+k) * 512 + nb + n4 * 4);
            Bs[k][n4*4+0]=b.x; Bs[k][n4*4+1]=b.y; Bs[k][n4*4+2]=b.z; Bs[k][n4*4+3]=b.w;
        }
        __syncthreads();
#pragma unroll
        for (int k = 0; k < 32; k++) {
            float4 a0 = *(const float4*)&As[k][m0];
            float4 a1 = *(const float4*)&As[k][m0+4];
            float2 bb = *(const float2*)&Bs[k][n0];
            float a[8] = {a0.x,a0.y,a0.z,a0.w,a1.x,a1.y,a1.z,a1.w};
#pragma unroll
            for (int i = 0; i < 8; i++) { acc[i][0] += a[i]*bb.x; acc[i][1] += a[i]*bb.y; }
        }
    }
#pragma unroll
    for (int i = 0; i < 8; i++) {
        g_v[(size_t)(m0+i)*Hz + nb+n0]   = acc[i][0];
        g_v[(size_t)(m0+i)*Hz + nb+n0+1] = acc[i][1];
    }
}

// ---------------------------------------------------------------------------
// K4: energy[s][b] = dot(v[b,:], enc[s,b,:]) + b_bil   (one warp per (s,b))
// ---------------------------------------------------------------------------
__global__ void __launch_bounds__(256) energy_kernel(
    const float* __restrict__ enc, const float* __restrict__ b_bil)
{
    int w = blockIdx.x * 8 + (threadIdx.x >> 5);
    int lane = threadIdx.x & 31;
    int s = w >> 7, b = w & 127;
    const float4* e4 = (const float4*)(enc + ((size_t)s * Bz + b) * Hz);
    const float4* v4 = (const float4*)(g_v + (size_t)b * Hz);
    float acc = 0.f;
#pragma unroll
    for (int i = 0; i < 4; i++) {
        float4 e = e4[lane + i * 32];
        float4 v = v4[lane + i * 32];
        acc += e.x*v.x + e.y*v.y + e.z*v.z + e.w*v.w;
    }
#pragma unroll
    for (int o = 16; o > 0; o >>= 1) acc += __shfl_xor_sync(0xffffffffu, acc, o);
    if (lane == 0) g_attn[(size_t)s * Bz + b] = acc + b_bil[0];
}

// ---------------------------------------------------------------------------
// K5: softmax over s per b; normalize g_attn in place + write enc_attn out
// ---------------------------------------------------------------------------
__global__ void attn_softmax(float* __restrict__ out)
{
    int b = blockIdx.x, t = threadIdx.x;
    __shared__ float red[128];
    float e0 = g_attn[(size_t)t * Bz + b];
    float e1 = g_attn[(size_t)(t + 128) * Bz + b];
    float e2 = g_attn[(size_t)(t + 256) * Bz + b];
    float e3 = (t < 16) ? g_attn[(size_t)(t + 384) * Bz + b] : -INFINITY;

    float m = fmaxf(fmaxf(e0, e1), fmaxf(e2, e3));
    red[t] = m; __syncthreads();
#pragma unroll
    for (int o = 64; o > 0; o >>= 1) { if (t < o) red[t] = fmaxf(red[t], red[t+o]); __syncthreads(); }
    float M = red[0]; __syncthreads();

    float x0 = expf(e0 - M), x1 = expf(e1 - M), x2 = expf(e2 - M);
    float x3 = (t < 16) ? expf(e3 - M) : 0.f;
    red[t] = x0 + x1 + x2 + x3; __syncthreads();
#pragma unroll
    for (int o = 64; o > 0; o >>= 1) { if (t < o) red[t] += red[t+o]; __syncthreads(); }
    float inv = 1.f / red[0];

    g_attn[(size_t)t * Bz + b]         = x0 * inv;
    g_attn[(size_t)(t + 128) * Bz + b] = x1 * inv;
    g_attn[(size_t)(t + 256) * Bz + b] = x2 * inv;
    out[OUT_ATTN + (size_t)b * Sz + t]       = x0 * inv;
    out[OUT_ATTN + (size_t)b * Sz + t + 128] = x1 * inv;
    out[OUT_ATTN + (size_t)b * Sz + t + 256] = x2 * inv;
    if (t < 16) {
        g_attn[(size_t)(t + 384) * Bz + b] = x3 * inv;
        out[OUT_ATTN + (size_t)b * Sz + t + 384] = x3 * inv;
    }
}

// ---------------------------------------------------------------------------
// K6: context[b] = sum_s attn[s][b]*enc[s,b,:]  -> g_comb[:, H:]; then p_ptr
// ---------------------------------------------------------------------------
__global__ void context_pptr(const float* __restrict__ enc,
                             const float* __restrict__ W_ptr,
                             const float* __restrict__ b_ptr,
                             float* __restrict__ out)
{
    int b = blockIdx.x, t = threadIdx.x;
    __shared__ float sa[Sz];
    __shared__ float red[128];
    for (int s = t; s < Sz; s += 128) sa[s] = g_attn[(size_t)s * Bz + b];
    __syncthreads();

    float4 acc = make_float4(0.f, 0.f, 0.f, 0.f);
#pragma unroll 4
    for (int s = 0; s < Sz; s++) {
        float a = sa[s];
        float4 e = *(const float4*)(enc + ((size_t)s * Bz + b) * Hz + t * 4);
        acc.x += a*e.x; acc.y += a*e.y; acc.z += a*e.z; acc.w += a*e.w;
    }
    *(float4*)(g_comb + (size_t)b * C2H + Hz + t * 4) = acc;
    __syncthreads();

    float p = 0.f;
    for (int j = t; j < C2H; j += 128) p += g_comb[(size_t)b * C2H + j] * W_ptr[j];
    red[t] = p; __syncthreads();
#pragma unroll
    for (int o = 64; o > 0; o >>= 1) { if (t < o) red[t] += red[t+o]; __syncthreads(); }
    if (t == 0) {
        float pp = sigf(red[0] + b_ptr[0]);
        g_pptr[b] = pp;
        out[OUT_PPTR + b] = pp;
    }
}

// ---------------------------------------------------------------------------
// K7: logits = g_comb[128,1024] @ W_out[V,1024]^T + b_out  via tf32 mma.sync
// ---------------------------------------------------------------------------
__device__ __forceinline__ uint32_t f2tf(float f) {
    uint32_t u; asm("cvt.rna.tf32.f32 %0, %1;" : "=r"(u) : "f"(f)); return u;
}

__global__ void __launch_bounds__(256) logits_kernel(
    const float* __restrict__ Wout, const float* __restrict__ bout)
{
    __shared__ uint32_t As[128][36];
    __shared__ uint32_t Bs[128][36];
    int tid = threadIdx.x;
    int warp = tid >> 5, lane = tid & 31;
    int gid = lane >> 2, t4 = lane & 3;
    int m0 = warp * 16;
    int vbase = blockIdx.x * 128;

    float acc[16][4] = {};

    for (int k0 = 0; k0 < C2H; k0 += 32) {
        __syncthreads();
#pragma unroll
        for (int i = 0; i < 4; i++) {
            int lin = tid + i * 256;
            int m = lin >> 3, k4 = lin & 7;
            float4 a = *(const float4*)(g_comb + (size_t)m * C2H + k0 + k4 * 4);
            uint4 ua = make_uint4(f2tf(a.x), f2tf(a.y), f2tf(a.z), f2tf(a.w));
            *(uint4*)&As[m][k4*4] = ua;
            int v = vbase + m;
            float4 bv = (v < Vz) ? *(const float4*)(Wout + (size_t)v * C2H + k0 + k4 * 4)
                                 : make_float4(0.f, 0.f, 0.f, 0.f);
            uint4 ub = make_uint4(f2tf(bv.x), f2tf(bv.y), f2tf(bv.z), f2tf(bv.w));
            *(uint4*)&Bs[m][k4*4] = ub;
        }
        __syncthreads();
#pragma unroll
        for (int kk = 0; kk < 32; kk += 8) {
            uint32_t a0 = As[m0+gid][kk+t4];
            uint32_t a1 = As[m0+gid+8][kk+t4];
            uint32_t a2 = As[m0+gid][kk+t4+4];
            uint32_t a3 = As[m0+gid+8][kk+t4+4];
#pragma unroll
            for (int nt = 0; nt < 16; nt++) {
                uint32_t b0 = Bs[nt*8+gid][kk+t4];
                uint32_t b1 = Bs[nt*8+gid][kk+t4+4];
                asm volatile(
                    "mma.sync.aligned.m16n8k8.row.col.f32.tf32.tf32.f32 "
                    "{%0,%1,%2,%3}, {%4,%5,%6,%7}, {%8,%9}, {%0,%1,%2,%3};"
                    : "+f"(acc[nt][0]), "+f"(acc[nt][1]), "+f"(acc[nt][2]), "+f"(acc[nt][3])
                    : "r"(a0), "r"(a1), "r"(a2), "r"(a3), "r"(b0), "r"(b1));
            }
        }
    }
#pragma unroll
    for (int nt = 0; nt < 16; nt++) {
        int v0 = vbase + nt * 8 + t4 * 2;
        if (v0 < Vz) {
            int m = m0 + gid;
            float bo0 = bout[v0], bo1 = bout[v0+1];
            g_logits[(size_t)m*Vz + v0]       = acc[nt][0] + bo0;
            g_logits[(size_t)m*Vz + v0+1]     = acc[nt][1] + bo1;
            g_logits[(size_t)(m+8)*Vz + v0]   = acc[nt][2] + bo0;
            g_logits[(size_t)(m+8)*Vz + v0+1] = acc[nt][3] + bo1;
        }
    }
}

// ---------------------------------------------------------------------------
// K8: per-b online max+sum over V logits
// ---------------------------------------------------------------------------
__global__ void __launch_bounds__(256) gen_reduce()
{
    int b = blockIdx.x, t = threadIdx.x;
    float m = -INFINITY, s = 0.f;
    for (int v = t; v < Vz; v += 256) {
        float x = g_logits[(size_t)b * Vz + v];
        if (x > m) { s = s * expf(m - x) + 1.f; m = x; }
        else       { s += expf(x - m); }
    }
    __shared__ float sm[256], ss[256];
    sm[t] = m; ss[t] = s; __syncthreads();
#pragma unroll
    for (int o = 128; o > 0; o >>= 1) {
        if (t < o) {
            float m2 = sm[t+o], s2 = ss[t+o];
            float M = fmaxf(sm[t], m2);
            ss[t] = ss[t] * expf(sm[t] - M) + s2 * expf(m2 - M);
            sm[t] = M;
        }
        __syncthreads();
    }
    if (t == 0) { g_mx[b] = sm[0]; g_inv[b] = 1.f / ss[0]; }
}

// ---------------------------------------------------------------------------
// K9: out[b][v] = (1-pp[b]) * exp(logit - mx[b]) * inv[b]
// ---------------------------------------------------------------------------
__global__ void base_write(float* __restrict__ out)
{
    int b = blockIdx.y;
    int j = blockIdx.x * 256 + threadIdx.x;
    if (j >= Vz / 4) return;
    float g = (1.f - g_pptr[b]) * g_inv[b];
    float m = g_mx[b];
    float4 l = *(const float4*)(g_logits + (size_t)b * Vz + j * 4);
    float4 r;
    r.x = g * expf(l.x - m);
    r.y = g * expf(l.y - m);
    r.z = g * expf(l.z - m);
    r.w = g * expf(l.w - m);
    *(float4*)(out + (size_t)b * Vz + j * 4) = r;
}

// ---------------------------------------------------------------------------
// K10: scatter-add pointer mass
// ---------------------------------------------------------------------------
__global__ void scatter_kernel(const int* __restrict__ widx, float* __restrict__ out)
{
    int i = blockIdx.x * 256 + threadIdx.x;  // i = s*B + b, exactly S*B threads
    int b = i & 127;
    float val = g_pptr[b] * g_attn[i];
    atomicAdd(out + (size_t)b * Vz + widx[i], val);
}

// ---------------------------------------------------------------------------
// K11: out = log(out) over [B,V]
// ---------------------------------------------------------------------------
__global__ void log_kernel(float* __restrict__ out)
{
    int b = blockIdx.y;
    int j = blockIdx.x * 256 + threadIdx.x;
    if (j >= Vz / 4) return;
    float4* p = (float4*)(out + (size_t)b * Vz + j * 4);
    float4 v = *p;
    v.x = logf(v.x); v.y = logf(v.y); v.z = logf(v.z); v.w = logf(v.w);
    *p = v;
}

// ---------------------------------------------------------------------------
extern "C" void kernel_launch(void* const* d_in, const int* in_sizes, int n_in,
                              void* d_out, int out_size)
{
    const float* emb  = (const float*)d_in[0];
    const float* hid  = (const float*)d_in[1];
    const float* enc  = (const float*)d_in[2];
    const int*   widx = (const int*)d_in[3];
    int base = (n_in >= 15) ? 5 : 4;  // skip ext_vocab_size scalar if present
    const float* W_ih  = (const float*)d_in[base+0];
    const float* W_hh  = (const float*)d_in[base+1];
    const float* b_ih  = (const float*)d_in[base+2];
    const float* b_hh  = (const float*)d_in[base+3];
    const float* W_bil = (const float*)d_in[base+4];
    const float* b_bil = (const float*)d_in[base+5];
    const float* W_out = (const float*)d_in[base+6];
    const float* b_out = (const float*)d_in[base+7];
    const float* W_ptr = (const float*)d_in[base+8];
    const float* b_ptr = (const float*)d_in[base+9];
    float* out = (float*)d_out;

    gemm_gru<<<dim3(96, 2), 128>>>(emb, W_ih, b_ih, hid, W_hh, b_hh);
    gru_gates<<<Bz, Hz>>>(hid, out);
    gemm_v<<<32, 128>>>(W_bil);
    energy_kernel<<<(Sz * Bz) / 8, 256>>>(enc, b_bil);
    attn_softmax<<<Bz, 128>>>(out);
    context_pptr<<<Bz, 128>>>(enc, W_ptr, b_ptr, out);
    logits_kernel<<<(Vz + 127) / 128, 256>>>(W_out, b_out);
    gen_reduce<<<Bz, 256>>>();
    base_write<<<dim3(49, Bz), 256>>>(out);
    scatter_kernel<<<(Sz * Bz) / 256, 256>>>(widx, out);
    log_kernel<<<dim3(49, Bz), 256>>>(out);
}

// round 5
// speedup vs baseline: 1.3290x; 1.3290x over previous
#include <cuda_runtime.h>
#include <cuda_fp16.h>
#include <stdint.h>
#include <math.h>

#define Bz 128
#define Sz 400
#define Ez 512
#define Hz 512
#define H3 1536
#define Vz 50000
#define C2H 1024

#define OUT_HID  ((size_t)Bz*Vz)
#define OUT_ATTN (OUT_HID + (size_t)Bz*Hz)
#define OUT_PPTR (OUT_ATTN + (size_t)Bz*Sz)

__device__ float g_gi[Bz*H3];
__device__ float g_gh[Bz*H3];
__device__ float g_hnew[Bz*Hz];
__device__ float g_v[Bz*Hz];
__device__ float g_comb[Bz*C2H];
__device__ __half g_combh[Bz*C2H];
__device__ float g_attn[Sz*Bz];
__device__ float g_logits[(size_t)Bz*Vz];
__device__ float g_pptr[Bz];
__device__ float g_mx[Bz];
__device__ float g_inv[Bz];

__device__ __forceinline__ float sigf(float x) { return 1.f / (1.f + expf(-x)); }

// ---------------------------------------------------------------------------
// K1: gi = emb @ W_ih^T + b_ih (y=0) ; gh = h @ W_hh^T + b_hh (y=1)
// ---------------------------------------------------------------------------
__global__ void __launch_bounds__(128) gemm_gru(
    const float* __restrict__ emb, const float* __restrict__ Wih,
    const float* __restrict__ bih, const float* __restrict__ hid,
    const float* __restrict__ Whh, const float* __restrict__ bhh)
{
    const float* A    = blockIdx.y ? hid  : emb;
    const float* Bm   = blockIdx.y ? Whh  : Wih;
    const float* bias = blockIdx.y ? bhh  : bih;
    float* C          = blockIdx.y ? g_gh : g_gi;

    __shared__ float As[32][132];
    __shared__ float Bs[32][16];
    int tid = threadIdx.x;
    int nb = blockIdx.x * 16;
    int m0 = (tid >> 3) * 8;
    int n0 = (tid & 7) * 2;
    float acc[8][2] = {};
    for (int k0 = 0; k0 < 512; k0 += 32) {
        __syncthreads();
#pragma unroll
        for (int i = 0; i < 8; i++) {
            int lin = tid + i * 128;
            int m = lin >> 3, k4 = lin & 7;
            float4 a = *(const float4*)(A + (size_t)m * 512 + k0 + k4 * 4);
            As[k4*4+0][m]=a.x; As[k4*4+1][m]=a.y; As[k4*4+2][m]=a.z; As[k4*4+3][m]=a.w;
        }
        {
            int n = tid >> 3, k4 = tid & 7;
            float4 b = *(const float4*)(Bm + (size_t)(nb+n) * 512 + k0 + k4 * 4);
            Bs[k4*4+0][n]=b.x; Bs[k4*4+1][n]=b.y; Bs[k4*4+2][n]=b.z; Bs[k4*4+3][n]=b.w;
        }
        __syncthreads();
#pragma unroll
        for (int k = 0; k < 32; k++) {
            float4 a0 = *(const float4*)&As[k][m0];
            float4 a1 = *(const float4*)&As[k][m0+4];
            float2 bb = *(const float2*)&Bs[k][n0];
            float a[8] = {a0.x,a0.y,a0.z,a0.w,a1.x,a1.y,a1.z,a1.w};
#pragma unroll
            for (int i = 0; i < 8; i++) { acc[i][0] += a[i]*bb.x; acc[i][1] += a[i]*bb.y; }
        }
    }
    float b0v = bias[nb+n0], b1v = bias[nb+n0+1];
#pragma unroll
    for (int i = 0; i < 8; i++) {
        C[(size_t)(m0+i)*H3 + nb+n0]   = acc[i][0] + b0v;
        C[(size_t)(m0+i)*H3 + nb+n0+1] = acc[i][1] + b1v;
    }
}

// ---------------------------------------------------------------------------
// K2: GRU gates -> h_new
// ---------------------------------------------------------------------------
__global__ void gru_gates(const float* __restrict__ hidden, float* __restrict__ out)
{
    int b = blockIdx.x, h = threadIdx.x;
    size_t r3 = (size_t)b * H3;
    float ir = g_gi[r3 + h],        hr = g_gh[r3 + h];
    float iz = g_gi[r3 + Hz + h],   hz = g_gh[r3 + Hz + h];
    float in_= g_gi[r3 + 2*Hz + h], hn = g_gh[r3 + 2*Hz + h];
    float r = sigf(ir + hr);
    float z = sigf(iz + hz);
    float n = tanhf(in_ + r * hn);
    float hp = hidden[(size_t)b * Hz + h];
    float hx = (1.f - z) * n + z * hp;
    g_hnew[(size_t)b * Hz + h] = hx;
    g_comb[(size_t)b * C2H + h] = hx;
    out[OUT_HID + (size_t)b * Hz + h] = hx;
}

// ---------------------------------------------------------------------------
// K3: v = h_new @ W_bil[0]
// ---------------------------------------------------------------------------
__global__ void __launch_bounds__(128) gemm_v(const float* __restrict__ Wbil)
{
    __shared__ float As[32][132];
    __shared__ float Bs[32][16];
    int tid = threadIdx.x;
    int nb = blockIdx.x * 16;
    int m0 = (tid >> 3) * 8;
    int n0 = (tid & 7) * 2;
    float acc[8][2] = {};
    for (int k0 = 0; k0 < 512; k0 += 32) {
        __syncthreads();
#pragma unroll
        for (int i = 0; i < 8; i++) {
            int lin = tid + i * 128;
            int m = lin >> 3, k4 = lin & 7;
            float4 a = *(const float4*)(g_hnew + (size_t)m * 512 + k0 + k4 * 4);
            As[k4*4+0][m]=a.x; As[k4*4+1][m]=a.y; As[k4*4+2][m]=a.z; As[k4*4+3][m]=a.w;
        }
        {
            int n4 = tid & 3, k = tid >> 2;
            float4 b = *(const float4*)(Wbil + (size_t)(k0+k) * 512 + nb + n4 * 4);
            Bs[k][n4*4+0]=b.x; Bs[k][n4*4+1]=b.y; Bs[k][n4*4+2]=b.z; Bs[k][n4*4+3]=b.w;
        }
        __syncthreads();
#pragma unroll
        for (int k = 0; k < 32; k++) {
            float4 a0 = *(const float4*)&As[k][m0];
            float4 a1 = *(const float4*)&As[k][m0+4];
            float2 bb = *(const float2*)&Bs[k][n0];
            float a[8] = {a0.x,a0.y,a0.z,a0.w,a1.x,a1.y,a1.z,a1.w};
#pragma unroll
            for (int i = 0; i < 8; i++) { acc[i][0] += a[i]*bb.x; acc[i][1] += a[i]*bb.y; }
        }
    }
#pragma unroll
    for (int i = 0; i < 8; i++) {
        g_v[(size_t)(m0+i)*Hz + nb+n0]   = acc[i][0];
        g_v[(size_t)(m0+i)*Hz + nb+n0+1] = acc[i][1];
    }
}

// ---------------------------------------------------------------------------
// K4: energy[s][b] = dot(v[b,:], enc[s,b,:]) + b_bil
// ---------------------------------------------------------------------------
__global__ void __launch_bounds__(256) energy_kernel(
    const float* __restrict__ enc, const float* __restrict__ b_bil)
{
    int w = blockIdx.x * 8 + (threadIdx.x >> 5);
    int lane = threadIdx.x & 31;
    int s = w >> 7, b = w & 127;
    const float4* e4 = (const float4*)(enc + ((size_t)s * Bz + b) * Hz);
    const float4* v4 = (const float4*)(g_v + (size_t)b * Hz);
    float acc = 0.f;
#pragma unroll
    for (int i = 0; i < 4; i++) {
        float4 e = e4[lane + i * 32];
        float4 v = v4[lane + i * 32];
        acc += e.x*v.x + e.y*v.y + e.z*v.z + e.w*v.w;
    }
#pragma unroll
    for (int o = 16; o > 0; o >>= 1) acc += __shfl_xor_sync(0xffffffffu, acc, o);
    if (lane == 0) g_attn[(size_t)s * Bz + b] = acc + b_bil[0];
}

// ---------------------------------------------------------------------------
// K5: softmax over s per b
// ---------------------------------------------------------------------------
__global__ void attn_softmax(float* __restrict__ out)
{
    int b = blockIdx.x, t = threadIdx.x;
    __shared__ float red[128];
    float e0 = g_attn[(size_t)t * Bz + b];
    float e1 = g_attn[(size_t)(t + 128) * Bz + b];
    float e2 = g_attn[(size_t)(t + 256) * Bz + b];
    float e3 = (t < 16) ? g_attn[(size_t)(t + 384) * Bz + b] : -INFINITY;

    float m = fmaxf(fmaxf(e0, e1), fmaxf(e2, e3));
    red[t] = m; __syncthreads();
#pragma unroll
    for (int o = 64; o > 0; o >>= 1) { if (t < o) red[t] = fmaxf(red[t], red[t+o]); __syncthreads(); }
    float M = red[0]; __syncthreads();

    float x0 = expf(e0 - M), x1 = expf(e1 - M), x2 = expf(e2 - M);
    float x3 = (t < 16) ? expf(e3 - M) : 0.f;
    red[t] = x0 + x1 + x2 + x3; __syncthreads();
#pragma unroll
    for (int o = 64; o > 0; o >>= 1) { if (t < o) red[t] += red[t+o]; __syncthreads(); }
    float inv = 1.f / red[0];

    g_attn[(size_t)t * Bz + b]         = x0 * inv;
    g_attn[(size_t)(t + 128) * Bz + b] = x1 * inv;
    g_attn[(size_t)(t + 256) * Bz + b] = x2 * inv;
    out[OUT_ATTN + (size_t)b * Sz + t]       = x0 * inv;
    out[OUT_ATTN + (size_t)b * Sz + t + 128] = x1 * inv;
    out[OUT_ATTN + (size_t)b * Sz + t + 256] = x2 * inv;
    if (t < 16) {
        g_attn[(size_t)(t + 384) * Bz + b] = x3 * inv;
        out[OUT_ATTN + (size_t)b * Sz + t + 384] = x3 * inv;
    }
}

// ---------------------------------------------------------------------------
// K6: context + p_ptr
// ---------------------------------------------------------------------------
__global__ void context_pptr(const float* __restrict__ enc,
                             const float* __restrict__ W_ptr,
                             const float* __restrict__ b_ptr,
                             float* __restrict__ out)
{
    int b = blockIdx.x, t = threadIdx.x;
    __shared__ float sa[Sz];
    __shared__ float red[128];
    for (int s = t; s < Sz; s += 128) sa[s] = g_attn[(size_t)s * Bz + b];
    __syncthreads();

    float4 acc = make_float4(0.f, 0.f, 0.f, 0.f);
#pragma unroll 4
    for (int s = 0; s < Sz; s++) {
        float a = sa[s];
        float4 e = *(const float4*)(enc + ((size_t)s * Bz + b) * Hz + t * 4);
        acc.x += a*e.x; acc.y += a*e.y; acc.z += a*e.z; acc.w += a*e.w;
    }
    *(float4*)(g_comb + (size_t)b * C2H + Hz + t * 4) = acc;
    __syncthreads();

    float p = 0.f;
    for (int j = t; j < C2H; j += 128) p += g_comb[(size_t)b * C2H + j] * W_ptr[j];
    red[t] = p; __syncthreads();
#pragma unroll
    for (int o = 64; o > 0; o >>= 1) { if (t < o) red[t] += red[t+o]; __syncthreads(); }
    if (t == 0) {
        float pp = sigf(red[0] + b_ptr[0]);
        g_pptr[b] = pp;
        out[OUT_PPTR + b] = pp;
    }
}

// ---------------------------------------------------------------------------
// K6b: convert combined to fp16
// ---------------------------------------------------------------------------
__global__ void conv_half()
{
    int i = blockIdx.x * 512 + threadIdx.x;
    float2 v = *(const float2*)(g_comb + i * 2);
    g_combh[i*2]   = __float2half(v.x);
    g_combh[i*2+1] = __float2half(v.y);
}

// ---------------------------------------------------------------------------
// K7: logits = comb[128,1024] @ W_out[V,1024]^T + b_out via fp16 mma.sync
//     m16n8k16, fp32 accum. Block: 256 thr (8 warps), tile M=128 x N=128,
//     K chunked by 64 through smem (half [128][72] padded).
//     Warp w handles rows [16w,16w+16), all 16 n-tiles of 8.
// ---------------------------------------------------------------------------
__global__ void __launch_bounds__(256) logits_mma(
    const float* __restrict__ Wout, const float* __restrict__ bout)
{
    __shared__ __half Ah[128][72];
    __shared__ __half Bh[128][72];
    int tid = threadIdx.x;
    int warp = tid >> 5, lane = tid & 31;
    int gid = lane >> 2, t4 = lane & 3;
    int m0 = warp * 16;
    int vbase = blockIdx.x * 128;
    bool full = (vbase + 128) <= Vz;

    float acc[16][4] = {};

    for (int k0 = 0; k0 < C2H; k0 += 64) {
        __syncthreads();
        // stage A: 128 rows x 64 halfs; 8 halfs (16B) per job, 1024 jobs
#pragma unroll
        for (int i = 0; i < 4; i++) {
            int j = tid + i * 256;
            int row = j >> 3, c8 = (j & 7) * 8;
            uint4 a = *(const uint4*)(g_combh + (size_t)row * C2H + k0 + c8);
            *(uint4*)&Ah[row][c8] = a;
        }
        // stage B: 128 vocab rows x 64 k, fp32 -> fp16
#pragma unroll
        for (int i = 0; i < 4; i++) {
            int j = tid + i * 256;
            int row = j >> 3, c8 = (j & 7) * 8;
            int v = vbase + row;
            uint4 packed = make_uint4(0, 0, 0, 0);
            if (full || v < Vz) {
                const float4* wp = (const float4*)(Wout + (size_t)v * C2H + k0 + c8);
                float4 w0 = wp[0], w1 = wp[1];
                __half2* h = (__half2*)&packed;
                h[0] = __floats2half2_rn(w0.x, w0.y);
                h[1] = __floats2half2_rn(w0.z, w0.w);
                h[2] = __floats2half2_rn(w1.x, w1.y);
                h[3] = __floats2half2_rn(w1.z, w1.w);
            }
            *(uint4*)&Bh[row][c8] = packed;
        }
        __syncthreads();
#pragma unroll
        for (int kk = 0; kk < 64; kk += 16) {
            uint32_t a0 = *(const uint32_t*)&Ah[m0 + gid][kk + t4 * 2];
            uint32_t a1 = *(const uint32_t*)&Ah[m0 + gid + 8][kk + t4 * 2];
            uint32_t a2 = *(const uint32_t*)&Ah[m0 + gid][kk + 8 + t4 * 2];
            uint32_t a3 = *(const uint32_t*)&Ah[m0 + gid + 8][kk + 8 + t4 * 2];
#pragma unroll
            for (int nt = 0; nt < 16; nt++) {
                uint32_t b0 = *(const uint32_t*)&Bh[nt * 8 + gid][kk + t4 * 2];
                uint32_t b1 = *(const uint32_t*)&Bh[nt * 8 + gid][kk + 8 + t4 * 2];
                asm volatile(
                    "mma.sync.aligned.m16n8k16.row.col.f32.f16.f16.f32 "
                    "{%0,%1,%2,%3}, {%4,%5,%6,%7}, {%8,%9}, {%0,%1,%2,%3};"
                    : "+f"(acc[nt][0]), "+f"(acc[nt][1]), "+f"(acc[nt][2]), "+f"(acc[nt][3])
                    : "r"(a0), "r"(a1), "r"(a2), "r"(a3), "r"(b0), "r"(b1));
            }
        }
    }
#pragma unroll
    for (int nt = 0; nt < 16; nt++) {
        int v0 = vbase + nt * 8 + t4 * 2;
        if (v0 < Vz) {
            int m = m0 + gid;
            float bo0 = bout[v0], bo1 = bout[v0 + 1];
            g_logits[(size_t)m * Vz + v0]         = acc[nt][0] + bo0;
            g_logits[(size_t)m * Vz + v0 + 1]     = acc[nt][1] + bo1;
            g_logits[(size_t)(m + 8) * Vz + v0]   = acc[nt][2] + bo0;
            g_logits[(size_t)(m + 8) * Vz + v0 + 1] = acc[nt][3] + bo1;
        }
    }
}

// ---------------------------------------------------------------------------
// K8: per-b online max+sum over V logits
// ---------------------------------------------------------------------------
__global__ void __launch_bounds__(256) gen_reduce()
{
    int b = blockIdx.x, t = threadIdx.x;
    float m = -INFINITY, s = 0.f;
    for (int v = t; v < Vz; v += 256) {
        float x = g_logits[(size_t)b * Vz + v];
        if (x > m) { s = s * expf(m - x) + 1.f; m = x; }
        else       { s += expf(x - m); }
    }
    __shared__ float sm[256], ss[256];
    sm[t] = m; ss[t] = s; __syncthreads();
#pragma unroll
    for (int o = 128; o > 0; o >>= 1) {
        if (t < o) {
            float m2 = sm[t+o], s2 = ss[t+o];
            float M = fmaxf(sm[t], m2);
            ss[t] = ss[t] * expf(sm[t] - M) + s2 * expf(m2 - M);
            sm[t] = M;
        }
        __syncthreads();
    }
    if (t == 0) { g_mx[b] = sm[0]; g_inv[b] = 1.f / ss[0]; }
}

// ---------------------------------------------------------------------------
// K9: out[b][v] = (1-pp)*exp(logit-mx)*inv
// ---------------------------------------------------------------------------
__global__ void base_write(float* __restrict__ out)
{
    int b = blockIdx.y;
    int j = blockIdx.x * 256 + threadIdx.x;
    if (j >= Vz / 4) return;
    float g = (1.f - g_pptr[b]) * g_inv[b];
    float m = g_mx[b];
    float4 l = *(const float4*)(g_logits + (size_t)b * Vz + j * 4);
    float4 r;
    r.x = g * expf(l.x - m);
    r.y = g * expf(l.y - m);
    r.z = g * expf(l.z - m);
    r.w = g * expf(l.w - m);
    *(float4*)(out + (size_t)b * Vz + j * 4) = r;
}

// ---------------------------------------------------------------------------
// K10: scatter-add pointer mass
// ---------------------------------------------------------------------------
__global__ void scatter_kernel(const int* __restrict__ widx, float* __restrict__ out)
{
    int i = blockIdx.x * 256 + threadIdx.x;
    int b = i & 127;
    float val = g_pptr[b] * g_attn[i];
    atomicAdd(out + (size_t)b * Vz + widx[i], val);
}

// ---------------------------------------------------------------------------
// K11: out = log(out)
// ---------------------------------------------------------------------------
__global__ void log_kernel(float* __restrict__ out)
{
    int b = blockIdx.y;
    int j = blockIdx.x * 256 + threadIdx.x;
    if (j >= Vz / 4) return;
    float4* p = (float4*)(out + (size_t)b * Vz + j * 4);
    float4 v = *p;
    v.x = logf(v.x); v.y = logf(v.y); v.z = logf(v.z); v.w = logf(v.w);
    *p = v;
}

// ---------------------------------------------------------------------------
extern "C" void kernel_launch(void* const* d_in, const int* in_sizes, int n_in,
                              void* d_out, int out_size)
{
    const float* emb  = (const float*)d_in[0];
    const float* hid  = (const float*)d_in[1];
    const float* enc  = (const float*)d_in[2];
    const int*   widx = (const int*)d_in[3];
    int base = (n_in >= 15) ? 5 : 4;
    const float* W_ih  = (const float*)d_in[base+0];
    const float* W_hh  = (const float*)d_in[base+1];
    const float* b_ih  = (const float*)d_in[base+2];
    const float* b_hh  = (const float*)d_in[base+3];
    const float* W_bil = (const float*)d_in[base+4];
    const float* b_bil = (const float*)d_in[base+5];
    const float* W_out = (const float*)d_in[base+6];
    const float* b_out = (const float*)d_in[base+7];
    const float* W_ptr = (const float*)d_in[base+8];
    const float* b_ptr = (const float*)d_in[base+9];
    float* out = (float*)d_out;

    gemm_gru<<<dim3(96, 2), 128>>>(emb, W_ih, b_ih, hid, W_hh, b_hh);
    gru_gates<<<Bz, Hz>>>(hid, out);
    gemm_v<<<32, 128>>>(W_bil);
    energy_kernel<<<(Sz * Bz) / 8, 256>>>(enc, b_bil);
    attn_softmax<<<Bz, 128>>>(out);
    context_pptr<<<Bz, 128>>>(enc, W_ptr, b_ptr, out);
    conv_half<<<(Bz * C2H) / 1024, 512>>>();
    logits_mma<<<(Vz + 127) / 128, 256>>>(W_out, b_out);
    gen_reduce<<<Bz, 256>>>();
    base_write<<<dim3(49, Bz), 256>>>(out);
    scatter_kernel<<<(Sz * Bz) / 256, 256>>>(widx, out);
    log_kernel<<<dim3(49, Bz), 256>>>(out);
}

// round 10
// speedup vs baseline: 1.3482x; 1.0144x over previous
#include <cuda_runtime.h>
#include <cuda_fp16.h>
#include <stdint.h>
#include <math.h>

#define Bz 128
#define Sz 400
#define Ez 512
#define Hz 512
#define H3 1536
#define Vz 50000
#define C2H 1024

#define OUT_HID  ((size_t)Bz*Vz)
#define OUT_ATTN (OUT_HID + (size_t)Bz*Hz)
#define OUT_PPTR (OUT_ATTN + (size_t)Bz*Sz)

__device__ float g_gi[Bz*H3];
__device__ float g_gh[Bz*H3];
__device__ float g_hnew[Bz*Hz];
__device__ float g_v[Bz*Hz];
__device__ float g_comb[Bz*C2H];
__device__ __half g_combh[Bz*C2H];
__device__ float g_attn[Sz*Bz];
__device__ float g_logits[(size_t)Bz*Vz];
__device__ float g_pptr[Bz];
__device__ float g_mx[Bz];
__device__ float g_inv[Bz];

__device__ __forceinline__ float sigf(float x) { return 1.f / (1.f + expf(-x)); }

// ---------------------------------------------------------------------------
// K1: gi = emb @ W_ih^T + b_ih (y=0) ; gh = h @ W_hh^T + b_hh (y=1)
// ---------------------------------------------------------------------------
__global__ void __launch_bounds__(128) gemm_gru(
    const float* __restrict__ emb, const float* __restrict__ Wih,
    const float* __restrict__ bih, const float* __restrict__ hid,
    const float* __restrict__ Whh, const float* __restrict__ bhh)
{
    const float* A    = blockIdx.y ? hid  : emb;
    const float* Bm   = blockIdx.y ? Whh  : Wih;
    const float* bias = blockIdx.y ? bhh  : bih;
    float* C          = blockIdx.y ? g_gh : g_gi;

    __shared__ float As[32][132];
    __shared__ float Bs[32][16];
    int tid = threadIdx.x;
    int nb = blockIdx.x * 16;
    int m0 = (tid >> 3) * 8;
    int n0 = (tid & 7) * 2;
    float acc[8][2] = {};
    for (int k0 = 0; k0 < 512; k0 += 32) {
        __syncthreads();
#pragma unroll
        for (int i = 0; i < 8; i++) {
            int lin = tid + i * 128;
            int m = lin >> 3, k4 = lin & 7;
            float4 a = *(const float4*)(A + (size_t)m * 512 + k0 + k4 * 4);
            As[k4*4+0][m]=a.x; As[k4*4+1][m]=a.y; As[k4*4+2][m]=a.z; As[k4*4+3][m]=a.w;
        }
        {
            int n = tid >> 3, k4 = tid & 7;
            float4 b = *(const float4*)(Bm + (size_t)(nb+n) * 512 + k0 + k4 * 4);
            Bs[k4*4+0][n]=b.x; Bs[k4*4+1][n]=b.y; Bs[k4*4+2][n]=b.z; Bs[k4*4+3][n]=b.w;
        }
        __syncthreads();
#pragma unroll
        for (int k = 0; k < 32; k++) {
            float4 a0 = *(const float4*)&As[k][m0];
            float4 a1 = *(const float4*)&As[k][m0+4];
            float2 bb = *(const float2*)&Bs[k][n0];
            float a[8] = {a0.x,a0.y,a0.z,a0.w,a1.x,a1.y,a1.z,a1.w};
#pragma unroll
            for (int i = 0; i < 8; i++) { acc[i][0] += a[i]*bb.x; acc[i][1] += a[i]*bb.y; }
        }
    }
    float b0v = bias[nb+n0], b1v = bias[nb+n0+1];
#pragma unroll
    for (int i = 0; i < 8; i++) {
        C[(size_t)(m0+i)*H3 + nb+n0]   = acc[i][0] + b0v;
        C[(size_t)(m0+i)*H3 + nb+n0+1] = acc[i][1] + b1v;
    }
}

// ---------------------------------------------------------------------------
// K2: GRU gates -> h_new
// ---------------------------------------------------------------------------
__global__ void gru_gates(const float* __restrict__ hidden, float* __restrict__ out)
{
    int b = blockIdx.x, h = threadIdx.x;
    size_t r3 = (size_t)b * H3;
    float ir = g_gi[r3 + h],        hr = g_gh[r3 + h];
    float iz = g_gi[r3 + Hz + h],   hz = g_gh[r3 + Hz + h];
    float in_= g_gi[r3 + 2*Hz + h], hn = g_gh[r3 + 2*Hz + h];
    float r = sigf(ir + hr);
    float z = sigf(iz + hz);
    float n = tanhf(in_ + r * hn);
    float hp = hidden[(size_t)b * Hz + h];
    float hx = (1.f - z) * n + z * hp;
    g_hnew[(size_t)b * Hz + h] = hx;
    g_comb[(size_t)b * C2H + h] = hx;
    out[OUT_HID + (size_t)b * Hz + h] = hx;
}

// ---------------------------------------------------------------------------
// K3: v = h_new @ W_bil[0]
// ---------------------------------------------------------------------------
__global__ void __launch_bounds__(128) gemm_v(const float* __restrict__ Wbil)
{
    __shared__ float As[32][132];
    __shared__ float Bs[32][16];
    int tid = threadIdx.x;
    int nb = blockIdx.x * 16;
    int m0 = (tid >> 3) * 8;
    int n0 = (tid & 7) * 2;
    float acc[8][2] = {};
    for (int k0 = 0; k0 < 512; k0 += 32) {
        __syncthreads();
#pragma unroll
        for (int i = 0; i < 8; i++) {
            int lin = tid + i * 128;
            int m = lin >> 3, k4 = lin & 7;
            float4 a = *(const float4*)(g_hnew + (size_t)m * 512 + k0 + k4 * 4);
            As[k4*4+0][m]=a.x; As[k4*4+1][m]=a.y; As[k4*4+2][m]=a.z; As[k4*4+3][m]=a.w;
        }
        {
            int n4 = tid & 3, k = tid >> 2;
            float4 b = *(const float4*)(Wbil + (size_t)(k0+k) * 512 + nb + n4 * 4);
            Bs[k][n4*4+0]=b.x; Bs[k][n4*4+1]=b.y; Bs[k][n4*4+2]=b.z; Bs[k][n4*4+3]=b.w;
        }
        __syncthreads();
#pragma unroll
        for (int k = 0; k < 32; k++) {
            float4 a0 = *(const float4*)&As[k][m0];
            float4 a1 = *(const float4*)&As[k][m0+4];
            float2 bb = *(const float2*)&Bs[k][n0];
            float a[8] = {a0.x,a0.y,a0.z,a0.w,a1.x,a1.y,a1.z,a1.w};
#pragma unroll
            for (int i = 0; i < 8; i++) { acc[i][0] += a[i]*bb.x; acc[i][1] += a[i]*bb.y; }
        }
    }
#pragma unroll
    for (int i = 0; i < 8; i++) {
        g_v[(size_t)(m0+i)*Hz + nb+n0]   = acc[i][0];
        g_v[(size_t)(m0+i)*Hz + nb+n0+1] = acc[i][1];
    }
}

// ---------------------------------------------------------------------------
// K4: energy[s][b] = dot(v[b,:], enc[s,b,:]) + b_bil
// ---------------------------------------------------------------------------
__global__ void __launch_bounds__(256) energy_kernel(
    const float* __restrict__ enc, const float* __restrict__ b_bil)
{
    int w = blockIdx.x * 8 + (threadIdx.x >> 5);
    int lane = threadIdx.x & 31;
    int s = w >> 7, b = w & 127;
    const float4* e4 = (const float4*)(enc + ((size_t)s * Bz + b) * Hz);
    const float4* v4 = (const float4*)(g_v + (size_t)b * Hz);
    float acc = 0.f;
#pragma unroll
    for (int i = 0; i < 4; i++) {
        float4 e = e4[lane + i * 32];
        float4 v = v4[lane + i * 32];
        acc += e.x*v.x + e.y*v.y + e.z*v.z + e.w*v.w;
    }
#pragma unroll
    for (int o = 16; o > 0; o >>= 1) acc += __shfl_xor_sync(0xffffffffu, acc, o);
    if (lane == 0) g_attn[(size_t)s * Bz + b] = acc + b_bil[0];
}

// ---------------------------------------------------------------------------
// K5: softmax over s per b
// ---------------------------------------------------------------------------
__global__ void attn_softmax(float* __restrict__ out)
{
    int b = blockIdx.x, t = threadIdx.x;
    __shared__ float red[128];
    float e0 = g_attn[(size_t)t * Bz + b];
    float e1 = g_attn[(size_t)(t + 128) * Bz + b];
    float e2 = g_attn[(size_t)(t + 256) * Bz + b];
    float e3 = (t < 16) ? g_attn[(size_t)(t + 384) * Bz + b] : -INFINITY;

    float m = fmaxf(fmaxf(e0, e1), fmaxf(e2, e3));
    red[t] = m; __syncthreads();
#pragma unroll
    for (int o = 64; o > 0; o >>= 1) { if (t < o) red[t] = fmaxf(red[t], red[t+o]); __syncthreads(); }
    float M = red[0]; __syncthreads();

    float x0 = expf(e0 - M), x1 = expf(e1 - M), x2 = expf(e2 - M);
    float x3 = (t < 16) ? expf(e3 - M) : 0.f;
    red[t] = x0 + x1 + x2 + x3; __syncthreads();
#pragma unroll
    for (int o = 64; o > 0; o >>= 1) { if (t < o) red[t] += red[t+o]; __syncthreads(); }
    float inv = 1.f / red[0];

    g_attn[(size_t)t * Bz + b]         = x0 * inv;
    g_attn[(size_t)(t + 128) * Bz + b] = x1 * inv;
    g_attn[(size_t)(t + 256) * Bz + b] = x2 * inv;
    out[OUT_ATTN + (size_t)b * Sz + t]       = x0 * inv;
    out[OUT_ATTN + (size_t)b * Sz + t + 128] = x1 * inv;
    out[OUT_ATTN + (size_t)b * Sz + t + 256] = x2 * inv;
    if (t < 16) {
        g_attn[(size_t)(t + 384) * Bz + b] = x3 * inv;
        out[OUT_ATTN + (size_t)b * Sz + t + 384] = x3 * inv;
    }
}

// ---------------------------------------------------------------------------
// K6: context + p_ptr
// ---------------------------------------------------------------------------
__global__ void context_pptr(const float* __restrict__ enc,
                             const float* __restrict__ W_ptr,
                             const float* __restrict__ b_ptr,
                             float* __restrict__ out)
{
    int b = blockIdx.x, t = threadIdx.x;
    __shared__ float sa[Sz];
    __shared__ float red[128];
    for (int s = t; s < Sz; s += 128) sa[s] = g_attn[(size_t)s * Bz + b];
    __syncthreads();

    float4 acc = make_float4(0.f, 0.f, 0.f, 0.f);
#pragma unroll 4
    for (int s = 0; s < Sz; s++) {
        float a = sa[s];
        float4 e = *(const float4*)(enc + ((size_t)s * Bz + b) * Hz + t * 4);
        acc.x += a*e.x; acc.y += a*e.y; acc.z += a*e.z; acc.w += a*e.w;
    }
    *(float4*)(g_comb + (size_t)b * C2H + Hz + t * 4) = acc;
    __syncthreads();

    float p = 0.f;
    for (int j = t; j < C2H; j += 128) p += g_comb[(size_t)b * C2H + j] * W_ptr[j];
    red[t] = p; __syncthreads();
#pragma unroll
    for (int o = 64; o > 0; o >>= 1) { if (t < o) red[t] += red[t+o]; __syncthreads(); }
    if (t == 0) {
        float pp = sigf(red[0] + b_ptr[0]);
        g_pptr[b] = pp;
        out[OUT_PPTR + b] = pp;
    }
}

// ---------------------------------------------------------------------------
// K6b: convert combined to fp16
// ---------------------------------------------------------------------------
__global__ void conv_half()
{
    int i = blockIdx.x * 512 + threadIdx.x;
    float2 v = *(const float2*)(g_comb + i * 2);
    g_combh[i*2]   = __float2half(v.x);
    g_combh[i*2+1] = __float2half(v.y);
}

// ---------------------------------------------------------------------------
// K7: logits = comb[128,1024] @ W_out[V,1024]^T + b_out via fp16 mma.sync
//     m16n8k16 with FP16 accumulation chained over K=64 (one smem chunk),
//     promoted to fp32 register accumulators once per chunk.
//     Block: 256 thr (8 warps), tile M=128 x N=128.
// ---------------------------------------------------------------------------
__global__ void __launch_bounds__(256) logits_mma(
    const float* __restrict__ Wout, const float* __restrict__ bout)
{
    __shared__ __half Ah[128][72];
    __shared__ __half Bh[128][72];
    int tid = threadIdx.x;
    int warp = tid >> 5, lane = tid & 31;
    int gid = lane >> 2, t4 = lane & 3;
    int m0 = warp * 16;
    int vbase = blockIdx.x * 128;
    bool full = (vbase + 128) <= Vz;

    float acc[16][4] = {};

    for (int k0 = 0; k0 < C2H; k0 += 64) {
        __syncthreads();
        // stage A: 128 rows x 64 halfs
#pragma unroll
        for (int i = 0; i < 4; i++) {
            int j = tid + i * 256;
            int row = j >> 3, c8 = (j & 7) * 8;
            uint4 a = *(const uint4*)(g_combh + (size_t)row * C2H + k0 + c8);
            *(uint4*)&Ah[row][c8] = a;
        }
        // stage B: 128 vocab rows x 64 k, fp32 -> fp16
#pragma unroll
        for (int i = 0; i < 4; i++) {
            int j = tid + i * 256;
            int row = j >> 3, c8 = (j & 7) * 8;
            int v = vbase + row;
            uint4 packed = make_uint4(0, 0, 0, 0);
            if (full || v < Vz) {
                const float4* wp = (const float4*)(Wout + (size_t)v * C2H + k0 + c8);
                float4 w0 = wp[0], w1 = wp[1];
                __half2* h = (__half2*)&packed;
                h[0] = __floats2half2_rn(w0.x, w0.y);
                h[1] = __floats2half2_rn(w0.z, w0.w);
                h[2] = __floats2half2_rn(w1.x, w1.y);
                h[3] = __floats2half2_rn(w1.z, w1.w);
            }
            *(uint4*)&Bh[row][c8] = packed;
        }
        __syncthreads();

        // preload all A operands for this chunk (4 k-steps x 4 regs)
        uint32_t areg[4][4];
#pragma unroll
        for (int q = 0; q < 4; q++) {
            areg[q][0] = *(const uint32_t*)&Ah[m0 + gid][q * 16 + t4 * 2];
            areg[q][1] = *(const uint32_t*)&Ah[m0 + gid + 8][q * 16 + t4 * 2];
            areg[q][2] = *(const uint32_t*)&Ah[m0 + gid][q * 16 + 8 + t4 * 2];
            areg[q][3] = *(const uint32_t*)&Ah[m0 + gid + 8][q * 16 + 8 + t4 * 2];
        }
#pragma unroll
        for (int nt = 0; nt < 16; nt++) {
            uint32_t c0 = 0, c1 = 0;   // fp16x2 accumulators (rows gid / gid+8)
#pragma unroll
            for (int q = 0; q < 4; q++) {
                uint32_t b0 = *(const uint32_t*)&Bh[nt * 8 + gid][q * 16 + t4 * 2];
                uint32_t b1 = *(const uint32_t*)&Bh[nt * 8 + gid][q * 16 + 8 + t4 * 2];
                asm volatile(
                    "mma.sync.aligned.m16n8k16.row.col.f16.f16.f16.f16 "
                    "{%0,%1}, {%2,%3,%4,%5}, {%6,%7}, {%0,%1};"
                    : "+r"(c0), "+r"(c1)
                    : "r"(areg[q][0]), "r"(areg[q][1]), "r"(areg[q][2]), "r"(areg[q][3]),
                      "r"(b0), "r"(b1));
            }
            float2 lo = __half22float2(*(__half2*)&c0);
            float2 hi = __half22float2(*(__half2*)&c1);
            acc[nt][0] += lo.x; acc[nt][1] += lo.y;
            acc[nt][2] += hi.x; acc[nt][3] += hi.y;
        }
    }
#pragma unroll
    for (int nt = 0; nt < 16; nt++) {
        int v0 = vbase + nt * 8 + t4 * 2;
        if (v0 < Vz) {
            int m = m0 + gid;
            float bo0 = bout[v0], bo1 = bout[v0 + 1];
            g_logits[(size_t)m * Vz + v0]           = acc[nt][0] + bo0;
            g_logits[(size_t)m * Vz + v0 + 1]       = acc[nt][1] + bo1;
            g_logits[(size_t)(m + 8) * Vz + v0]     = acc[nt][2] + bo0;
            g_logits[(size_t)(m + 8) * Vz + v0 + 1] = acc[nt][3] + bo1;
        }
    }
}

// ---------------------------------------------------------------------------
// K8: per-b online max+sum over V logits
// ---------------------------------------------------------------------------
__global__ void __launch_bounds__(256) gen_reduce()
{
    int b = blockIdx.x, t = threadIdx.x;
    float m = -INFINITY, s = 0.f;
    for (int v = t; v < Vz; v += 256) {
        float x = g_logits[(size_t)b * Vz + v];
        if (x > m) { s = s * expf(m - x) + 1.f; m = x; }
        else       { s += expf(x - m); }
    }
    __shared__ float sm[256], ss[256];
    sm[t] = m; ss[t] = s; __syncthreads();
#pragma unroll
    for (int o = 128; o > 0; o >>= 1) {
        if (t < o) {
            float m2 = sm[t+o], s2 = ss[t+o];
            float M = fmaxf(sm[t], m2);
            ss[t] = ss[t] * expf(sm[t] - M) + s2 * expf(m2 - M);
            sm[t] = M;
        }
        __syncthreads();
    }
    if (t == 0) { g_mx[b] = sm[0]; g_inv[b] = 1.f / ss[0]; }
}

// ---------------------------------------------------------------------------
// K9: out[b][v] = (1-pp)*exp(logit-mx)*inv
// ---------------------------------------------------------------------------
__global__ void base_write(float* __restrict__ out)
{
    int b = blockIdx.y;
    int j = blockIdx.x * 256 + threadIdx.x;
    if (j >= Vz / 4) return;
    float g = (1.f - g_pptr[b]) * g_inv[b];
    float m = g_mx[b];
    float4 l = *(const float4*)(g_logits + (size_t)b * Vz + j * 4);
    float4 r;
    r.x = g * expf(l.x - m);
    r.y = g * expf(l.y - m);
    r.z = g * expf(l.z - m);
    r.w = g * expf(l.w - m);
    *(float4*)(out + (size_t)b * Vz + j * 4) = r;
}

// ---------------------------------------------------------------------------
// K10: scatter-add pointer mass
// ---------------------------------------------------------------------------
__global__ void scatter_kernel(const int* __restrict__ widx, float* __restrict__ out)
{
    int i = blockIdx.x * 256 + threadIdx.x;
    int b = i & 127;
    float val = g_pptr[b] * g_attn[i];
    atomicAdd(out + (size_t)b * Vz + widx[i], val);
}

// ---------------------------------------------------------------------------
// K11: out = log(out)
// ---------------------------------------------------------------------------
__global__ void log_kernel(float* __restrict__ out)
{
    int b = blockIdx.y;
    int j = blockIdx.x * 256 + threadIdx.x;
    if (j >= Vz / 4) return;
    float4* p = (float4*)(out + (size_t)b * Vz + j * 4);
    float4 v = *p;
    v.x = logf(v.x); v.y = logf(v.y); v.z = logf(v.z); v.w = logf(v.w);
    *p = v;
}

// ---------------------------------------------------------------------------
extern "C" void kernel_launch(void* const* d_in, const int* in_sizes, int n_in,
                              void* d_out, int out_size)
{
    const float* emb  = (const float*)d_in[0];
    const float* hid  = (const float*)d_in[1];
    const float* enc  = (const float*)d_in[2];
    const int*   widx = (const int*)d_in[3];
    int base = (n_in >= 15) ? 5 : 4;
    const float* W_ih  = (const float*)d_in[base+0];
    const float* W_hh  = (const float*)d_in[base+1];
    const float* b_ih  = (const float*)d_in[base+2];
    const float* b_hh  = (const float*)d_in[base+3];
    const float* W_bil = (const float*)d_in[base+4];
    const float* b_bil = (const float*)d_in[base+5];
    const float* W_out = (const float*)d_in[base+6];
    const float* b_out = (const float*)d_in[base+7];
    const float* W_ptr = (const float*)d_in[base+8];
    const float* b_ptr = (const float*)d_in[base+9];
    float* out = (float*)d_out;

    gemm_gru<<<dim3(96, 2), 128>>>(emb, W_ih, b_ih, hid, W_hh, b_hh);
    gru_gates<<<Bz, Hz>>>(hid, out);
    gemm_v<<<32, 128>>>(W_bil);
    energy_kernel<<<(Sz * Bz) / 8, 256>>>(enc, b_bil);
    attn_softmax<<<Bz, 128>>>(out);
    context_pptr<<<Bz, 128>>>(enc, W_ptr, b_ptr, out);
    conv_half<<<(Bz * C2H) / 1024, 512>>>();
    logits_mma<<<(Vz + 127) / 128, 256>>>(W_out, b_out);
    gen_reduce<<<Bz, 256>>>();
    base_write<<<dim3(49, Bz), 256>>>(out);
    scatter_kernel<<<(Sz * Bz) / 256, 256>>>(widx, out);
    log_kernel<<<dim3(49, Bz), 256>>>(out);
}